// round 5
// baseline (speedup 1.0000x reference)
#include <cuda_runtime.h>
#include <cstdint>

#define NR 65536
typedef unsigned long long ull;

__device__ float g_c[(size_t)NR * 160];
__device__ float g_u[(size_t)NR * 1024];
__device__ float g_hA[(size_t)NR * 512];
__device__ float g_hB[(size_t)NR * 512];
__device__ float g_x[NR];

__device__ __forceinline__ ull pack2(float x, float y) {
    ull r; asm("mov.b64 %0, {%1, %2};" : "=l"(r) : "f"(x), "f"(y)); return r;
}
__device__ __forceinline__ void unpack2(ull v, float& x, float& y) {
    asm("mov.b64 {%0, %1}, %2;" : "=f"(x), "=f"(y) : "l"(v));
}
__device__ __forceinline__ void fma2(ull& d, ull a, ull b) {
    asm("fma.rn.f32x2 %0, %1, %2, %0;" : "+l"(d) : "l"(a), "l"(b));
}
__device__ __forceinline__ float sig_(float x) { return 1.0f / (1.0f + expf(-x)); }
__device__ __forceinline__ float gelu_(float x) {
    return 0.5f * x * (1.0f + erff(x * 0.70710678f));
}

// ---------------- concat(z_q, f_prior) -> g_c (N x 160) ----------------
__global__ void k_concat(const float* __restrict__ z, const float* __restrict__ f) {
    size_t i = (size_t)blockIdx.x * blockDim.x + threadIdx.x;
    if (i >= (size_t)NR * 160) return;
    int row = (int)(i / 160), col = (int)(i % 160);
    g_c[i] = (col < 128) ? z[(size_t)row * 128 + col] : f[(size_t)row * 32 + col - 128];
}

// ---------------- generic GEMM: out = act(A[M x K] @ W[K x n] + b) ----------------
// 128x128 tile, BK=8, 256 threads, 8x8 per thread (f32x2). act: 0=none, 1=tanh
__global__ __launch_bounds__(256) void k_gemm_act(
    const float* __restrict__ A, int K,
    const float* __restrict__ W, int ldw, const float* __restrict__ bias,
    float* __restrict__ O, int ldo, int act)
{
    __shared__ float As[8][128];
    __shared__ float Bs[8][128];
    const int bJ = blockIdx.x, bM = blockIdx.y, tid = threadIdx.x;
    const int tx = tid & 15, ty = tid >> 4;
    const int la_i = tid >> 1, la_k = (tid & 1) * 4;
    const int lb_k = tid >> 5, lb_j = (tid & 31) * 4;
    const size_t arow = (size_t)(bM * 128 + la_i);

    ull acc[8][4];
#pragma unroll
    for (int r = 0; r < 8; ++r)
#pragma unroll
        for (int c = 0; c < 4; ++c) acc[r][c] = 0ULL;

    float4 pa = *(const float4*)(A + arow * K + la_k);
    float4 pb = *(const float4*)(W + (size_t)lb_k * ldw + bJ * 128 + lb_j);
    const int NIT = K / 8;
    for (int it = 0; it < NIT; ++it) {
        __syncthreads();
        As[la_k + 0][la_i] = pa.x; As[la_k + 1][la_i] = pa.y;
        As[la_k + 2][la_i] = pa.z; As[la_k + 3][la_i] = pa.w;
        *(float4*)&Bs[lb_k][lb_j] = pb;
        __syncthreads();
        if (it + 1 < NIT) {
            int k0 = (it + 1) * 8;
            pa = *(const float4*)(A + arow * K + k0 + la_k);
            pb = *(const float4*)(W + (size_t)(k0 + lb_k) * ldw + bJ * 128 + lb_j);
        }
#pragma unroll
        for (int k = 0; k < 8; ++k) {
            float4 a0 = *(const float4*)&As[k][ty * 4];
            float4 a1 = *(const float4*)&As[k][64 + ty * 4];
            ull aa[8] = { pack2(a0.x,a0.x), pack2(a0.y,a0.y), pack2(a0.z,a0.z), pack2(a0.w,a0.w),
                          pack2(a1.x,a1.x), pack2(a1.y,a1.y), pack2(a1.z,a1.z), pack2(a1.w,a1.w) };
            ull b0  = *(const ull*)&Bs[k][tx * 4];
            ull b1v = *(const ull*)&Bs[k][tx * 4 + 2];
            ull b2v = *(const ull*)&Bs[k][64 + tx * 4];
            ull b3v = *(const ull*)&Bs[k][64 + tx * 4 + 2];
#pragma unroll
            for (int r = 0; r < 8; ++r) {
                fma2(acc[r][0], aa[r], b0);  fma2(acc[r][1], aa[r], b1v);
                fma2(acc[r][2], aa[r], b2v); fma2(acc[r][3], aa[r], b3v);
            }
        }
    }
    const int c0 = bJ * 128 + tx * 4;
    float bi[8];
#pragma unroll
    for (int c = 0; c < 4; ++c) { bi[c] = bias[c0 + c]; bi[c + 4] = bias[c0 + 64 + c]; }
#pragma unroll
    for (int r = 0; r < 8; ++r) {
        int row = bM * 128 + ((r < 4) ? (ty * 4 + r) : (64 + ty * 4 + r - 4));
        float v[8];
        unpack2(acc[r][0], v[0], v[1]); unpack2(acc[r][1], v[2], v[3]);
        unpack2(acc[r][2], v[4], v[5]); unpack2(acc[r][3], v[6], v[7]);
#pragma unroll
        for (int c = 0; c < 8; ++c) {
            float o = v[c] + bi[c];
            v[c] = act ? tanhf(o) : o;
        }
        *(float4*)&O[(size_t)row * ldo + c0]      = make_float4(v[0], v[1], v[2], v[3]);
        *(float4*)&O[(size_t)row * ldo + c0 + 64] = make_float4(v[4], v[5], v[6], v[7]);
    }
}

// ---------------- u = gelu(LN(u)), rows of 1024 ----------------
__global__ __launch_bounds__(256) void k_lngelu(
    const float* __restrict__ g1, const float* __restrict__ be1)
{
    const size_t row = blockIdx.x;
    const int tid = threadIdx.x, lane = tid & 31, w = tid >> 5;
    float* up = g_u + row * 1024 + tid * 4;
    float4 v = *(float4*)up;
    __shared__ float red[8];
    float s = v.x + v.y + v.z + v.w;
#pragma unroll
    for (int m = 16; m >= 1; m >>= 1) s += __shfl_xor_sync(~0u, s, m);
    if (lane == 0) red[w] = s;
    __syncthreads();
    float tot = 0.f;
#pragma unroll
    for (int i = 0; i < 8; ++i) tot += red[i];
    const float mean = tot * (1.0f / 1024.0f);
    float dx = v.x - mean, dy = v.y - mean, dz = v.z - mean, dw = v.w - mean;
    float q = dx * dx + dy * dy + dz * dz + dw * dw;
#pragma unroll
    for (int m = 16; m >= 1; m >>= 1) q += __shfl_xor_sync(~0u, q, m);
    __syncthreads();
    if (lane == 0) red[w] = q;
    __syncthreads();
    float qt = 0.f;
#pragma unroll
    for (int i = 0; i < 8; ++i) qt += red[i];
    const float rstd = rsqrtf(qt * (1.0f / 1024.0f) + 1e-5f);
    const int j = tid * 4;
    float4 g4 = *(const float4*)&g1[j];
    float4 b4 = *(const float4*)&be1[j];
    float4 o;
    o.x = gelu_(dx * rstd * g4.x + b4.x);
    o.y = gelu_(dy * rstd * g4.y + b4.y);
    o.z = gelu_(dz * rstd * g4.z + b4.z);
    o.w = gelu_(dw * rstd * g4.w + b4.w);
    *(float4*)up = o;
}

__global__ void k_setx(const float* __restrict__ st) {
    int i = blockIdx.x * blockDim.x + threadIdx.x;
    if (i < NR) g_x[i] = st[0];
}

// ---------------- fused GRU step ----------------
// Block: 128 rows x 64 j-cols x 3 gates. bJ fast in grid for h L2 reuse.
__global__ __launch_bounds__(256) void k_gru(
    const float* __restrict__ W_hh, const float* __restrict__ W_ih,
    const float* __restrict__ b_ih, const float* __restrict__ b_hh, int t)
{
    const float* __restrict__ hIn  = (t & 1) ? g_hB : g_hA;
    float* __restrict__       hOut = (t & 1) ? g_hA : g_hB;
    __shared__ float As[8][128];
    __shared__ float Bs[3][8][64];
    const int bJ = blockIdx.x, bM = blockIdx.y, tid = threadIdx.x;
    const int tx = tid & 15, ty = tid >> 4;
    const int la_i = tid >> 1, la_k = (tid & 1) * 4;
    const size_t arow = (size_t)(bM * 128 + la_i);
    const int bg = tid >> 6, bjl = tid & 63;
    const bool bload = (tid < 192);
    const float* wrow = W_hh + (size_t)(bg * 512 + bJ * 64 + bjl) * 512;

    ull acc[3][8][2];
#pragma unroll
    for (int g = 0; g < 3; ++g)
#pragma unroll
        for (int r = 0; r < 8; ++r) { acc[g][r][0] = 0ULL; acc[g][r][1] = 0ULL; }

    float4 pa = *(const float4*)(hIn + arow * 512 + la_k);
    float4 pb0 = make_float4(0,0,0,0), pb1 = make_float4(0,0,0,0);
    if (bload) { pb0 = *(const float4*)(wrow); pb1 = *(const float4*)(wrow + 4); }

    for (int it = 0; it < 64; ++it) {
        __syncthreads();
        As[la_k + 0][la_i] = pa.x; As[la_k + 1][la_i] = pa.y;
        As[la_k + 2][la_i] = pa.z; As[la_k + 3][la_i] = pa.w;
        if (bload) {
            Bs[bg][0][bjl] = pb0.x; Bs[bg][1][bjl] = pb0.y;
            Bs[bg][2][bjl] = pb0.z; Bs[bg][3][bjl] = pb0.w;
            Bs[bg][4][bjl] = pb1.x; Bs[bg][5][bjl] = pb1.y;
            Bs[bg][6][bjl] = pb1.z; Bs[bg][7][bjl] = pb1.w;
        }
        __syncthreads();
        if (it + 1 < 64) {
            int k0 = (it + 1) * 8;
            pa = *(const float4*)(hIn + arow * 512 + k0 + la_k);
            if (bload) { pb0 = *(const float4*)(wrow + k0); pb1 = *(const float4*)(wrow + k0 + 4); }
        }
#pragma unroll
        for (int k = 0; k < 8; ++k) {
            float4 a0 = *(const float4*)&As[k][ty * 4];
            float4 a1 = *(const float4*)&As[k][64 + ty * 4];
            ull aa[8] = { pack2(a0.x,a0.x), pack2(a0.y,a0.y), pack2(a0.z,a0.z), pack2(a0.w,a0.w),
                          pack2(a1.x,a1.x), pack2(a1.y,a1.y), pack2(a1.z,a1.z), pack2(a1.w,a1.w) };
#pragma unroll
            for (int g = 0; g < 3; ++g) {
                ull b0  = *(const ull*)&Bs[g][k][tx * 4];
                ull b1v = *(const ull*)&Bs[g][k][tx * 4 + 2];
#pragma unroll
                for (int r = 0; r < 8; ++r) { fma2(acc[g][r][0], aa[r], b0); fma2(acc[g][r][1], aa[r], b1v); }
            }
        }
    }

    const int j0 = bJ * 64 + tx * 4;
    float wr[4], wz[4], wn[4], bir[4], biz[4], bin_[4], bhr[4], bhz[4], bhn[4];
#pragma unroll
    for (int c = 0; c < 4; ++c) {
        int j = j0 + c;
        wr[c] = W_ih[j];   wz[c] = W_ih[512 + j];   wn[c] = W_ih[1024 + j];
        bir[c] = b_ih[j];  biz[c] = b_ih[512 + j];  bin_[c] = b_ih[1024 + j];
        bhr[c] = b_hh[j];  bhz[c] = b_hh[512 + j];  bhn[c] = b_hh[1024 + j];
    }
#pragma unroll
    for (int r = 0; r < 8; ++r) {
        int row = bM * 128 + ((r < 4) ? (ty * 4 + r) : (64 + ty * 4 + r - 4));
        float xi = g_x[row];
        float4 hold = *(const float4*)(hIn + (size_t)row * 512 + j0);
        float ho[4] = { hold.x, hold.y, hold.z, hold.w };
        float ghr[4], ghz[4], ghn[4], ov[4];
        unpack2(acc[0][r][0], ghr[0], ghr[1]); unpack2(acc[0][r][1], ghr[2], ghr[3]);
        unpack2(acc[1][r][0], ghz[0], ghz[1]); unpack2(acc[1][r][1], ghz[2], ghz[3]);
        unpack2(acc[2][r][0], ghn[0], ghn[1]); unpack2(acc[2][r][1], ghn[2], ghn[3]);
#pragma unroll
        for (int c = 0; c < 4; ++c) {
            float rr = sig_(fmaf(xi, wr[c], bir[c]) + ghr[c] + bhr[c]);
            float zz = sig_(fmaf(xi, wz[c], biz[c]) + ghz[c] + bhz[c]);
            float nn = tanhf(fmaf(xi, wn[c], bin_[c]) + rr * (ghn[c] + bhn[c]));
            ov[c] = (1.0f - zz) * nn + zz * ho[c];
        }
        *(float4*)(hOut + (size_t)row * 512 + j0) = make_float4(ov[0], ov[1], ov[2], ov[3]);
    }
}

// ---------------- fused output MLP: y = gelu(LN(h@Wo1+bo1)) @ Wo2 + bo2 ----------------
// Block: 64 rows x 256 cols. Each warp owns 8 rows; row's 256 cols spread over 32 lanes.
__global__ __launch_bounds__(256) void k_out(
    const float* __restrict__ Wo1, const float* __restrict__ bo1,
    const float* __restrict__ go, const float* __restrict__ beo,
    const float* __restrict__ Wo2, const float* __restrict__ bo2,
    float* __restrict__ out, int t)
{
    const float* __restrict__ hNew = (t & 1) ? g_hA : g_hB;
    __shared__ float As[8][64];
    __shared__ float Bs[8][256];
    const int bM = blockIdx.x, tid = threadIdx.x;
    const int lane = tid & 31, w = tid >> 5;
    const int la_i = tid >> 2, la_k = (tid & 3) * 2;
    const int lb_k = tid >> 5, lb_j = lane * 8;
    const size_t arow = (size_t)(bM * 64 + la_i);

    ull acc[8][4];
#pragma unroll
    for (int r = 0; r < 8; ++r)
#pragma unroll
        for (int c = 0; c < 4; ++c) acc[r][c] = 0ULL;

    float2 pa = *(const float2*)(hNew + arow * 512 + la_k);
    float4 pb0 = *(const float4*)(Wo1 + (size_t)lb_k * 256 + lb_j);
    float4 pb1 = *(const float4*)(Wo1 + (size_t)lb_k * 256 + lb_j + 4);
    for (int it = 0; it < 64; ++it) {
        __syncthreads();
        As[la_k][la_i] = pa.x; As[la_k + 1][la_i] = pa.y;
        *(float4*)&Bs[lb_k][lb_j] = pb0;
        *(float4*)&Bs[lb_k][lb_j + 4] = pb1;
        __syncthreads();
        if (it + 1 < 64) {
            int k0 = (it + 1) * 8;
            pa = *(const float2*)(hNew + arow * 512 + k0 + la_k);
            pb0 = *(const float4*)(Wo1 + (size_t)(k0 + lb_k) * 256 + lb_j);
            pb1 = *(const float4*)(Wo1 + (size_t)(k0 + lb_k) * 256 + lb_j + 4);
        }
#pragma unroll
        for (int k = 0; k < 8; ++k) {
            float4 a0 = *(const float4*)&As[k][w * 4];
            float4 a1 = *(const float4*)&As[k][32 + w * 4];
            ull aa[8] = { pack2(a0.x,a0.x), pack2(a0.y,a0.y), pack2(a0.z,a0.z), pack2(a0.w,a0.w),
                          pack2(a1.x,a1.x), pack2(a1.y,a1.y), pack2(a1.z,a1.z), pack2(a1.w,a1.w) };
            ull b0  = *(const ull*)&Bs[k][lane * 4];
            ull b1v = *(const ull*)&Bs[k][lane * 4 + 2];
            ull b2v = *(const ull*)&Bs[k][128 + lane * 4];
            ull b3v = *(const ull*)&Bs[k][128 + lane * 4 + 2];
#pragma unroll
            for (int r = 0; r < 8; ++r) {
                fma2(acc[r][0], aa[r], b0);  fma2(acc[r][1], aa[r], b1v);
                fma2(acc[r][2], aa[r], b2v); fma2(acc[r][3], aa[r], b3v);
            }
        }
    }

    const int jA = lane * 4, jB = 128 + lane * 4;
    float bo1v[8], gov[8], beov[8], wo2v[8];
#pragma unroll
    for (int c = 0; c < 4; ++c) {
        bo1v[c] = bo1[jA + c]; bo1v[c + 4] = bo1[jB + c];
        gov[c]  = go[jA + c];  gov[c + 4]  = go[jB + c];
        beov[c] = beo[jA + c]; beov[c + 4] = beo[jB + c];
        wo2v[c] = Wo2[jA + c]; wo2v[c + 4] = Wo2[jB + c];
    }
    const float bo2v = bo2[0];
#pragma unroll
    for (int r = 0; r < 8; ++r) {
        int row = bM * 64 + ((r < 4) ? (w * 4 + r) : (32 + w * 4 + r - 4));
        float v[8];
        unpack2(acc[r][0], v[0], v[1]); unpack2(acc[r][1], v[2], v[3]);
        unpack2(acc[r][2], v[4], v[5]); unpack2(acc[r][3], v[6], v[7]);
        float s = 0.f;
#pragma unroll
        for (int c = 0; c < 8; ++c) { v[c] += bo1v[c]; s += v[c]; }
#pragma unroll
        for (int m = 16; m >= 1; m >>= 1) s += __shfl_xor_sync(~0u, s, m);
        float mean = s * (1.0f / 256.0f);
        float q = 0.f;
#pragma unroll
        for (int c = 0; c < 8; ++c) { float d = v[c] - mean; q += d * d; }
#pragma unroll
        for (int m = 16; m >= 1; m >>= 1) q += __shfl_xor_sync(~0u, q, m);
        float rstd = rsqrtf(q * (1.0f / 256.0f) + 1e-5f);
        float y = 0.f;
#pragma unroll
        for (int c = 0; c < 8; ++c) {
            float ln = (v[c] - mean) * rstd * gov[c] + beov[c];
            y += gelu_(ln) * wo2v[c];
        }
#pragma unroll
        for (int m = 16; m >= 1; m >>= 1) y += __shfl_xor_sync(~0u, y, m);
        if (lane == 0) {
            float yy = y + bo2v;
            out[(size_t)row * 20 + t] = yy;
            g_x[row] = yy;
        }
    }
}

extern "C" void kernel_launch(void* const* d_in, const int* in_sizes, int n_in,
                              void* d_out, int out_size) {
    const float* z_q   = (const float*)d_in[0];
    const float* f_pr  = (const float*)d_in[1];
    const float* W1    = (const float*)d_in[2];
    const float* b1    = (const float*)d_in[3];
    const float* g1    = (const float*)d_in[4];
    const float* be1   = (const float*)d_in[5];
    const float* W2    = (const float*)d_in[6];
    const float* b2    = (const float*)d_in[7];
    const float* start = (const float*)d_in[8];
    const float* W_ih  = (const float*)d_in[9];
    const float* W_hh  = (const float*)d_in[10];
    const float* b_ih  = (const float*)d_in[11];
    const float* b_hh  = (const float*)d_in[12];
    const float* Wo1   = (const float*)d_in[13];
    const float* bo1   = (const float*)d_in[14];
    const float* go    = (const float*)d_in[15];
    const float* beo   = (const float*)d_in[16];
    const float* Wo2   = (const float*)d_in[17];
    const float* bo2   = (const float*)d_in[18];
    float* out = (float*)d_out;

    float *uP, *cP;
    cudaGetSymbolAddress((void**)&cP, g_c);
    cudaGetSymbolAddress((void**)&uP, g_u);
    float *hAP, *hBP;
    cudaGetSymbolAddress((void**)&hAP, g_hA);
    cudaGetSymbolAddress((void**)&hBP, g_hB);

    k_concat<<<(int)(((size_t)NR * 160 + 255) / 256), 256>>>(z_q, f_pr);
    k_gemm_act<<<dim3(8, NR / 128), 256>>>(cP, 160, W1, 1024, b1, uP, 1024, 0);
    k_lngelu<<<NR, 256>>>(g1, be1);
    k_gemm_act<<<dim3(4, NR / 128), 256>>>(uP, 1024, W2, 512, b2, hAP, 512, 1);
    k_setx<<<NR / 256, 256>>>(start);
    for (int t = 0; t < 20; ++t) {
        k_gru<<<dim3(8, NR / 128), 256>>>(W_hh, W_ih, b_ih, b_hh, t);
        k_out<<<NR / 64, 256>>>(Wo1, bo1, go, beo, Wo2, bo2, out, t);
    }
}

// round 7
// speedup vs baseline: 1.9801x; 1.9801x over previous
#include <cuda_runtime.h>
#include <cuda_bf16.h>
#include <cstdint>

#define NR 65536
typedef unsigned long long ull;
typedef __nv_bfloat16 bf16;

// ----------------------------- device scratch ------------------------------
__device__ float g_c[(size_t)NR * 160];
__device__ float g_u[(size_t)NR * 1024];
__device__ float g_hA[(size_t)NR * 512];
__device__ float g_hB[(size_t)NR * 512];
__device__ bf16  g_hiA[(size_t)NR * 512];
__device__ bf16  g_loA[(size_t)NR * 512];
__device__ bf16  g_hiB[(size_t)NR * 512];
__device__ bf16  g_loB[(size_t)NR * 512];
__device__ float g_v[(size_t)NR * 256];
__device__ float g_x[NR];
__device__ bf16  g_WhhHi[1536 * 512];
__device__ bf16  g_WhhLo[1536 * 512];
__device__ bf16  g_Wo1Hi[256 * 512];   // transposed [N=256, K=512]
__device__ bf16  g_Wo1Lo[256 * 512];

// ----------------------------- small helpers -------------------------------
__device__ __forceinline__ ull pack2(float x, float y) {
    ull r; asm("mov.b64 %0, {%1, %2};" : "=l"(r) : "f"(x), "f"(y)); return r;
}
__device__ __forceinline__ void unpack2(ull v, float& x, float& y) {
    asm("mov.b64 {%0, %1}, %2;" : "=f"(x), "=f"(y) : "l"(v));
}
__device__ __forceinline__ void fma2(ull& d, ull a, ull b) {
    asm("fma.rn.f32x2 %0, %1, %2, %0;" : "+l"(d) : "l"(a), "l"(b));
}
__device__ __forceinline__ float sig_(float x) { return 1.0f / (1.0f + expf(-x)); }
__device__ __forceinline__ float gelu_(float x) {
    return 0.5f * x * (1.0f + erff(x * 0.70710678f));
}
__device__ __forceinline__ uint32_t smem_u32(const void* p) {
    uint32_t a;
    asm("{ .reg .u64 t; cvta.to.shared.u64 t, %1; cvt.u32.u64 %0, t; }" : "=r"(a) : "l"(p));
    return a;
}
__device__ __forceinline__ uint32_t swz(uint32_t off) { return off ^ ((off >> 3) & 0x70); }

__device__ __forceinline__ void cpasync16(uint32_t saddr, const void* gptr) {
    asm volatile("{ .reg .u64 g; cvta.to.global.u64 g, %1; "
                 "cp.async.cg.shared.global [%0], [g], 16; }"
                 :: "r"(saddr), "l"(gptr) : "memory");
}
#define CP_COMMIT() asm volatile("cp.async.commit_group;" ::: "memory")
#define CP_WAIT1()  asm volatile("cp.async.wait_group 1;" ::: "memory")
#define CP_WAIT0()  asm volatile("cp.async.wait_group 0;" ::: "memory")

__device__ __forceinline__ void ldmx4(uint32_t* r, uint32_t addr) {
    asm volatile("ldmatrix.sync.aligned.m8n8.x4.shared.b16 {%0,%1,%2,%3}, [%4];"
        : "=r"(r[0]), "=r"(r[1]), "=r"(r[2]), "=r"(r[3]) : "r"(addr));
}
__device__ __forceinline__ void mma_bf16(float* d, const uint32_t* a, const uint32_t* b) {
    asm volatile("mma.sync.aligned.m16n8k16.row.col.f32.bf16.bf16.f32 "
        "{%0,%1,%2,%3}, {%4,%5,%6,%7}, {%8,%9}, {%0,%1,%2,%3};"
        : "+f"(d[0]), "+f"(d[1]), "+f"(d[2]), "+f"(d[3])
        : "r"(a[0]), "r"(a[1]), "r"(a[2]), "r"(a[3]), "r"(b[0]), "r"(b[1]));
}

// =========================== init-path SIMT kernels =========================
__global__ void k_concat(const float* __restrict__ z, const float* __restrict__ f) {
    size_t i = (size_t)blockIdx.x * blockDim.x + threadIdx.x;
    if (i >= (size_t)NR * 160) return;
    int row = (int)(i / 160), col = (int)(i % 160);
    g_c[i] = (col < 128) ? z[(size_t)row * 128 + col] : f[(size_t)row * 32 + col - 128];
}

__global__ __launch_bounds__(256) void k_gemm_act(
    const float* __restrict__ A, int K,
    const float* __restrict__ W, int ldw, const float* __restrict__ bias,
    float* __restrict__ O, int ldo, int act)
{
    __shared__ float As[8][128];
    __shared__ float Bs[8][128];
    const int bJ = blockIdx.x, bM = blockIdx.y, tid = threadIdx.x;
    const int tx = tid & 15, ty = tid >> 4;
    const int la_i = tid >> 1, la_k = (tid & 1) * 4;
    const int lb_k = tid >> 5, lb_j = (tid & 31) * 4;
    const size_t arow = (size_t)(bM * 128 + la_i);
    ull acc[8][4];
#pragma unroll
    for (int r = 0; r < 8; ++r)
#pragma unroll
        for (int c = 0; c < 4; ++c) acc[r][c] = 0ULL;
    float4 pa = *(const float4*)(A + arow * K + la_k);
    float4 pb = *(const float4*)(W + (size_t)lb_k * ldw + bJ * 128 + lb_j);
    const int NIT = K / 8;
    for (int it = 0; it < NIT; ++it) {
        __syncthreads();
        As[la_k + 0][la_i] = pa.x; As[la_k + 1][la_i] = pa.y;
        As[la_k + 2][la_i] = pa.z; As[la_k + 3][la_i] = pa.w;
        *(float4*)&Bs[lb_k][lb_j] = pb;
        __syncthreads();
        if (it + 1 < NIT) {
            int k0 = (it + 1) * 8;
            pa = *(const float4*)(A + arow * K + k0 + la_k);
            pb = *(const float4*)(W + (size_t)(k0 + lb_k) * ldw + bJ * 128 + lb_j);
        }
#pragma unroll
        for (int k = 0; k < 8; ++k) {
            float4 a0 = *(const float4*)&As[k][ty * 4];
            float4 a1 = *(const float4*)&As[k][64 + ty * 4];
            ull aa[8] = { pack2(a0.x,a0.x), pack2(a0.y,a0.y), pack2(a0.z,a0.z), pack2(a0.w,a0.w),
                          pack2(a1.x,a1.x), pack2(a1.y,a1.y), pack2(a1.z,a1.z), pack2(a1.w,a1.w) };
            ull b0  = *(const ull*)&Bs[k][tx * 4];
            ull b1v = *(const ull*)&Bs[k][tx * 4 + 2];
            ull b2v = *(const ull*)&Bs[k][64 + tx * 4];
            ull b3v = *(const ull*)&Bs[k][64 + tx * 4 + 2];
#pragma unroll
            for (int r = 0; r < 8; ++r) {
                fma2(acc[r][0], aa[r], b0);  fma2(acc[r][1], aa[r], b1v);
                fma2(acc[r][2], aa[r], b2v); fma2(acc[r][3], aa[r], b3v);
            }
        }
    }
    const int c0 = bJ * 128 + tx * 4;
    float bi[8];
#pragma unroll
    for (int c = 0; c < 4; ++c) { bi[c] = bias[c0 + c]; bi[c + 4] = bias[c0 + 64 + c]; }
#pragma unroll
    for (int r = 0; r < 8; ++r) {
        int row = bM * 128 + ((r < 4) ? (ty * 4 + r) : (64 + ty * 4 + r - 4));
        float v[8];
        unpack2(acc[r][0], v[0], v[1]); unpack2(acc[r][1], v[2], v[3]);
        unpack2(acc[r][2], v[4], v[5]); unpack2(acc[r][3], v[6], v[7]);
#pragma unroll
        for (int c = 0; c < 8; ++c) {
            float o = v[c] + bi[c];
            v[c] = act ? tanhf(o) : o;
        }
        *(float4*)&O[(size_t)row * ldo + c0]      = make_float4(v[0], v[1], v[2], v[3]);
        *(float4*)&O[(size_t)row * ldo + c0 + 64] = make_float4(v[4], v[5], v[6], v[7]);
    }
}

__global__ __launch_bounds__(256) void k_lngelu(
    const float* __restrict__ g1, const float* __restrict__ be1)
{
    const size_t row = blockIdx.x;
    const int tid = threadIdx.x, lane = tid & 31, w = tid >> 5;
    float* up = g_u + row * 1024 + tid * 4;
    float4 v = *(float4*)up;
    __shared__ float red[8];
    float s = v.x + v.y + v.z + v.w;
#pragma unroll
    for (int m = 16; m >= 1; m >>= 1) s += __shfl_xor_sync(~0u, s, m);
    if (lane == 0) red[w] = s;
    __syncthreads();
    float tot = 0.f;
#pragma unroll
    for (int i = 0; i < 8; ++i) tot += red[i];
    const float mean = tot * (1.0f / 1024.0f);
    float dx = v.x - mean, dy = v.y - mean, dz = v.z - mean, dw = v.w - mean;
    float q = dx * dx + dy * dy + dz * dz + dw * dw;
#pragma unroll
    for (int m = 16; m >= 1; m >>= 1) q += __shfl_xor_sync(~0u, q, m);
    __syncthreads();
    if (lane == 0) red[w] = q;
    __syncthreads();
    float qt = 0.f;
#pragma unroll
    for (int i = 0; i < 8; ++i) qt += red[i];
    const float rstd = rsqrtf(qt * (1.0f / 1024.0f) + 1e-5f);
    const int j = tid * 4;
    float4 g4 = *(const float4*)&g1[j];
    float4 b4 = *(const float4*)&be1[j];
    float4 o;
    o.x = gelu_(dx * rstd * g4.x + b4.x);
    o.y = gelu_(dy * rstd * g4.y + b4.y);
    o.z = gelu_(dz * rstd * g4.z + b4.z);
    o.w = gelu_(dw * rstd * g4.w + b4.w);
    *(float4*)up = o;
}

__global__ void k_setx(const float* __restrict__ st) {
    int i = blockIdx.x * blockDim.x + threadIdx.x;
    if (i < NR) g_x[i] = st[0];
}

__global__ void k_split(const float* __restrict__ src, bf16* __restrict__ hi,
                        bf16* __restrict__ lo, int n) {
    int i = blockIdx.x * blockDim.x + threadIdx.x;
    if (i >= n) return;
    float x = src[i];
    bf16 h = __float2bfloat16(x);
    hi[i] = h;
    lo[i] = __float2bfloat16(x - __bfloat162float(h));
}
__global__ void k_splitWoT(const float* __restrict__ Wo1) {
    int i = blockIdx.x * blockDim.x + threadIdx.x;   // over 512*256
    if (i >= 512 * 256) return;
    int k = i >> 8, n = i & 255;
    float x = Wo1[i];
    bf16 h = __float2bfloat16(x);
    g_Wo1Hi[n * 512 + k] = h;
    g_Wo1Lo[n * 512 + k] = __float2bfloat16(x - __bfloat162float(h));
}

// ============================ GRU step (mma.sync) ===========================
// CTA: 128 rows x 64 j-cols x 3 gates. K=512 in 8 chunks of 64, cp.async
// double-buffered. Each warp: 64 rows x 16 j-cols x 3 gates -> gate math fully
// in-register in the epilogue.
// SMEM: A[buf][hl] @ b*32768 + hl*16384 (128 rows x 128B, SW128)
//       B[buf][hl] @ 65536 + b*49152 + hl*24576 (192 rows x 128B, SW128)
#define GRU_SMEM (160 * 1024)

__device__ __forceinline__ void gru_copy(uint32_t sb, int c, int b, int bM, int bJ,
                                         int tid, const bf16* hiIn, const bf16* loIn) {
#pragma unroll
    for (int i = 0; i < 8; ++i) {
        int seg = tid + 256 * i, hl = seg >> 10, rem = seg & 1023, row = rem >> 3, s = rem & 7;
        const bf16* src = (hl ? loIn : hiIn) + (size_t)(bM * 128 + row) * 512 + c * 64 + s * 8;
        cpasync16(sb + b * 32768 + hl * 16384 + swz(row * 128 + s * 16), src);
    }
#pragma unroll
    for (int i = 0; i < 12; ++i) {
        int seg = tid + 256 * i;
        int hl = seg >= 1536 ? 1 : 0, rem = seg - hl * 1536, row = rem >> 3, s = rem & 7;
        int grow = (row >> 6) * 512 + bJ * 64 + (row & 63);
        const bf16* src = (hl ? g_WhhLo : g_WhhHi) + (size_t)grow * 512 + c * 64 + s * 8;
        cpasync16(sb + 65536 + b * 49152 + hl * 24576 + swz(row * 128 + s * 16), src);
    }
}

__global__ __launch_bounds__(256, 1) void k_gru_mma(
    const float* __restrict__ W_ih, const float* __restrict__ b_ih,
    const float* __restrict__ b_hh, int t)
{
    extern __shared__ char smem[];
    const float* hIn   = (t & 1) ? g_hB : g_hA;
    float*       hOut  = (t & 1) ? g_hA : g_hB;
    const bf16*  hiIn  = (t & 1) ? g_hiB : g_hiA;
    const bf16*  loIn  = (t & 1) ? g_loB : g_loA;
    bf16*        hiOut = (t & 1) ? g_hiA : g_hiB;
    bf16*        loOut = (t & 1) ? g_loA : g_loB;

    const int bJ = blockIdx.x, bM = blockIdx.y, tid = threadIdx.x;
    const int wid = tid >> 5, lane = tid & 31;
    const int mgrp = wid >> 2, ngrp = wid & 3;
    uint32_t sb = smem_u32(smem);

    float acc[3][4][2][4];
#pragma unroll
    for (int g = 0; g < 3; ++g)
#pragma unroll
        for (int mt = 0; mt < 4; ++mt)
#pragma unroll
            for (int nt = 0; nt < 2; ++nt)
#pragma unroll
                for (int c = 0; c < 4; ++c) acc[g][mt][nt][c] = 0.f;

    gru_copy(sb, 0, 0, bM, bJ, tid, hiIn, loIn);
    CP_COMMIT();

    for (int c = 0; c < 8; ++c) {
        int b = c & 1;
        if (c + 1 < 8) { gru_copy(sb, c + 1, b ^ 1, bM, bJ, tid, hiIn, loIn); CP_COMMIT(); CP_WAIT1(); }
        else CP_WAIT0();
        __syncthreads();
#pragma unroll
        for (int ks = 0; ks < 4; ++ks) {
            uint32_t aH[4][4], aL[4][4];
#pragma unroll
            for (int mt = 0; mt < 4; ++mt) {
                int arow = mgrp * 64 + mt * 16 + (lane & 15);
                uint32_t off = swz(arow * 128 + ks * 32 + (lane >> 4) * 16);
                ldmx4(aH[mt], sb + b * 32768 + off);
                ldmx4(aL[mt], sb + b * 32768 + 16384 + off);
            }
#pragma unroll
            for (int g = 0; g < 3; ++g) {
                int brow = g * 64 + ngrp * 16 + (lane & 7) + ((lane >> 4) & 1) * 8;
                uint32_t boff = swz(brow * 128 + ks * 32 + ((lane >> 3) & 1) * 16);
                uint32_t bH[4], bL[4];
                ldmx4(bH, sb + 65536 + b * 49152 + boff);
                ldmx4(bL, sb + 65536 + b * 49152 + 24576 + boff);
#pragma unroll
                for (int mt = 0; mt < 4; ++mt)
#pragma unroll
                    for (int nt = 0; nt < 2; ++nt) {
                        mma_bf16(acc[g][mt][nt], aH[mt], bH + nt * 2);
                        mma_bf16(acc[g][mt][nt], aH[mt], bL + nt * 2);
                        mma_bf16(acc[g][mt][nt], aL[mt], bH + nt * 2);
                    }
            }
        }
        __syncthreads();
    }

    // ---- in-register gate epilogue ----
#pragma unroll
    for (int nt = 0; nt < 2; ++nt) {
        const int j = bJ * 64 + ngrp * 16 + nt * 8 + (lane & 3) * 2;
        float wih[3][2], bih[3][2], bhh[3][2];
#pragma unroll
        for (int g = 0; g < 3; ++g)
#pragma unroll
            for (int cc = 0; cc < 2; ++cc) {
                wih[g][cc] = W_ih[g * 512 + j + cc];
                bih[g][cc] = b_ih[g * 512 + j + cc];
                bhh[g][cc] = b_hh[g * 512 + j + cc];
            }
#pragma unroll
        for (int mt = 0; mt < 4; ++mt)
#pragma unroll
            for (int half = 0; half < 2; ++half) {
                int row = bM * 128 + mgrp * 64 + mt * 16 + (lane >> 2) + half * 8;
                float xi = g_x[row];
                float2 hOld = *(const float2*)(hIn + (size_t)row * 512 + j);
                float hn[2];
#pragma unroll
                for (int cc = 0; cc < 2; ++cc) {
                    float ghr = acc[0][mt][nt][half * 2 + cc];
                    float ghz = acc[1][mt][nt][half * 2 + cc];
                    float ghn = acc[2][mt][nt][half * 2 + cc];
                    float rr = sig_(fmaf(xi, wih[0][cc], bih[0][cc]) + ghr + bhh[0][cc]);
                    float zz = sig_(fmaf(xi, wih[1][cc], bih[1][cc]) + ghz + bhh[1][cc]);
                    float nn = tanhf(fmaf(xi, wih[2][cc], bih[2][cc]) + rr * (ghn + bhh[2][cc]));
                    hn[cc] = (1.0f - zz) * nn + zz * (cc ? hOld.y : hOld.x);
                }
                *(float2*)(hOut + (size_t)row * 512 + j) = make_float2(hn[0], hn[1]);
                bf16 h0 = __float2bfloat16(hn[0]), h1 = __float2bfloat16(hn[1]);
                bf16 l0 = __float2bfloat16(hn[0] - __bfloat162float(h0));
                bf16 l1 = __float2bfloat16(hn[1] - __bfloat162float(h1));
                __nv_bfloat162 hh; hh.x = h0; hh.y = h1;
                __nv_bfloat162 ll; ll.x = l0; ll.y = l1;
                *(__nv_bfloat162*)(hiOut + (size_t)row * 512 + j) = hh;
                *(__nv_bfloat162*)(loOut + (size_t)row * 512 + j) = ll;
            }
    }
}

// ========================= output GEMM (mma.sync) ===========================
// CTA: 128 rows x 64 n-cols, grid (4, 512). Warp: 64m x 16n.
// SMEM: A @ b*32768 + hl*16384 ; B @ 65536 + b*16384 + hl*8192. Total 96KB.
#define OUT_SMEM (96 * 1024)

__device__ __forceinline__ void out_copy(uint32_t sb, int c, int b, int bM, int bJ,
                                         int tid, const bf16* hiIn, const bf16* loIn) {
#pragma unroll
    for (int i = 0; i < 8; ++i) {
        int seg = tid + 256 * i, hl = seg >> 10, rem = seg & 1023, row = rem >> 3, s = rem & 7;
        const bf16* src = (hl ? loIn : hiIn) + (size_t)(bM * 128 + row) * 512 + c * 64 + s * 8;
        cpasync16(sb + b * 32768 + hl * 16384 + swz(row * 128 + s * 16), src);
    }
#pragma unroll
    for (int i = 0; i < 4; ++i) {
        int seg = tid + 256 * i, hl = seg >> 9, rem = seg & 511, row = rem >> 3, s = rem & 7;
        int grow = bJ * 64 + row;
        const bf16* src = (hl ? g_Wo1Lo : g_Wo1Hi) + (size_t)grow * 512 + c * 64 + s * 8;
        cpasync16(sb + 65536 + b * 16384 + hl * 8192 + swz(row * 128 + s * 16), src);
    }
}

__global__ __launch_bounds__(256, 1) void k_out_mma(int t)
{
    extern __shared__ char smem[];
    const bf16* hiIn = (t & 1) ? g_hiA : g_hiB;   // h_new side
    const bf16* loIn = (t & 1) ? g_loA : g_loB;
    const int bJ = blockIdx.x, bM = blockIdx.y, tid = threadIdx.x;
    const int wid = tid >> 5, lane = tid & 31;
    const int mgrp = wid >> 2, ngrp = wid & 3;
    uint32_t sb = smem_u32(smem);

    float acc[4][2][4];
#pragma unroll
    for (int mt = 0; mt < 4; ++mt)
#pragma unroll
        for (int nt = 0; nt < 2; ++nt)
#pragma unroll
            for (int c = 0; c < 4; ++c) acc[mt][nt][c] = 0.f;

    out_copy(sb, 0, 0, bM, bJ, tid, hiIn, loIn);
    CP_COMMIT();

    for (int c = 0; c < 8; ++c) {
        int b = c & 1;
        if (c + 1 < 8) { out_copy(sb, c + 1, b ^ 1, bM, bJ, tid, hiIn, loIn); CP_COMMIT(); CP_WAIT1(); }
        else CP_WAIT0();
        __syncthreads();
#pragma unroll
        for (int ks = 0; ks < 4; ++ks) {
            uint32_t aH[4][4], aL[4][4];
#pragma unroll
            for (int mt = 0; mt < 4; ++mt) {
                int arow = mgrp * 64 + mt * 16 + (lane & 15);
                uint32_t off = swz(arow * 128 + ks * 32 + (lane >> 4) * 16);
                ldmx4(aH[mt], sb + b * 32768 + off);
                ldmx4(aL[mt], sb + b * 32768 + 16384 + off);
            }
            int brow = ngrp * 16 + (lane & 7) + ((lane >> 4) & 1) * 8;
            uint32_t boff = swz(brow * 128 + ks * 32 + ((lane >> 3) & 1) * 16);
            uint32_t bH[4], bL[4];
            ldmx4(bH, sb + 65536 + b * 16384 + boff);
            ldmx4(bL, sb + 65536 + b * 16384 + 8192 + boff);
#pragma unroll
            for (int mt = 0; mt < 4; ++mt)
#pragma unroll
                for (int nt = 0; nt < 2; ++nt) {
                    mma_bf16(acc[mt][nt], aH[mt], bH + nt * 2);
                    mma_bf16(acc[mt][nt], aH[mt], bL + nt * 2);
                    mma_bf16(acc[mt][nt], aL[mt], bH + nt * 2);
                }
        }
        __syncthreads();
    }

#pragma unroll
    for (int nt = 0; nt < 2; ++nt) {
        const int n = bJ * 64 + ngrp * 16 + nt * 8 + (lane & 3) * 2;
#pragma unroll
        for (int mt = 0; mt < 4; ++mt)
#pragma unroll
            for (int half = 0; half < 2; ++half) {
                int row = bM * 128 + mgrp * 64 + mt * 16 + (lane >> 2) + half * 8;
                *(float2*)(g_v + (size_t)row * 256 + n) =
                    make_float2(acc[mt][nt][half * 2], acc[mt][nt][half * 2 + 1]);
            }
    }
}

// --------- output finalize: LN + GELU + dot(Wo2) + bias -> out, x ----------
__global__ __launch_bounds__(256) void k_outfin(
    const float* __restrict__ bo1, const float* __restrict__ go,
    const float* __restrict__ beo, const float* __restrict__ Wo2,
    const float* __restrict__ bo2, float* __restrict__ out, int t)
{
    const int tid = threadIdx.x, wid = tid >> 5, lane = tid & 31;
    const int row = blockIdx.x * 8 + wid;
    const float* vr = g_v + (size_t)row * 256 + lane * 8;
    float v[8];
    float4 a = *(const float4*)vr, b = *(const float4*)(vr + 4);
    v[0]=a.x; v[1]=a.y; v[2]=a.z; v[3]=a.w; v[4]=b.x; v[5]=b.y; v[6]=b.z; v[7]=b.w;
    const int j0 = lane * 8;
    float s = 0.f;
#pragma unroll
    for (int c = 0; c < 8; ++c) { v[c] += bo1[j0 + c]; s += v[c]; }
#pragma unroll
    for (int m = 16; m >= 1; m >>= 1) s += __shfl_xor_sync(~0u, s, m);
    float mean = s * (1.0f / 256.0f);
    float q = 0.f;
#pragma unroll
    for (int c = 0; c < 8; ++c) { float d = v[c] - mean; q += d * d; }
#pragma unroll
    for (int m = 16; m >= 1; m >>= 1) q += __shfl_xor_sync(~0u, q, m);
    float rstd = rsqrtf(q * (1.0f / 256.0f) + 1e-5f);
    float y = 0.f;
#pragma unroll
    for (int c = 0; c < 8; ++c) {
        float ln = (v[c] - mean) * rstd * go[j0 + c] + beo[j0 + c];
        y += gelu_(ln) * Wo2[j0 + c];
    }
#pragma unroll
    for (int m = 16; m >= 1; m >>= 1) y += __shfl_xor_sync(~0u, y, m);
    if (lane == 0) {
        float yy = y + bo2[0];
        out[(size_t)row * 20 + t] = yy;
        g_x[row] = yy;
    }
}

// ================================== host ====================================
extern "C" void kernel_launch(void* const* d_in, const int* in_sizes, int n_in,
                              void* d_out, int out_size) {
    const float* z_q   = (const float*)d_in[0];
    const float* f_pr  = (const float*)d_in[1];
    const float* W1    = (const float*)d_in[2];
    const float* b1    = (const float*)d_in[3];
    const float* g1    = (const float*)d_in[4];
    const float* be1   = (const float*)d_in[5];
    const float* W2    = (const float*)d_in[6];
    const float* b2    = (const float*)d_in[7];
    const float* start = (const float*)d_in[8];
    const float* W_ih  = (const float*)d_in[9];
    const float* W_hh  = (const float*)d_in[10];
    const float* b_ih  = (const float*)d_in[11];
    const float* b_hh  = (const float*)d_in[12];
    const float* Wo1   = (const float*)d_in[13];
    const float* bo1   = (const float*)d_in[14];
    const float* go    = (const float*)d_in[15];
    const float* beo   = (const float*)d_in[16];
    const float* Wo2   = (const float*)d_in[17];
    const float* bo2   = (const float*)d_in[18];
    float* out = (float*)d_out;

    cudaFuncSetAttribute(k_gru_mma, cudaFuncAttributeMaxDynamicSharedMemorySize, GRU_SMEM);
    cudaFuncSetAttribute(k_out_mma, cudaFuncAttributeMaxDynamicSharedMemorySize, OUT_SMEM);

    float *cP, *uP, *hAP;
    cudaGetSymbolAddress((void**)&cP, g_c);
    cudaGetSymbolAddress((void**)&uP, g_u);
    cudaGetSymbolAddress((void**)&hAP, g_hA);
    bf16 *hiAP, *loAP, *whhHiP, *whhLoP;
    cudaGetSymbolAddress((void**)&hiAP, g_hiA);
    cudaGetSymbolAddress((void**)&loAP, g_loA);
    cudaGetSymbolAddress((void**)&whhHiP, g_WhhHi);
    cudaGetSymbolAddress((void**)&whhLoP, g_WhhLo);

    // weight prep
    k_split<<<(1536 * 512 + 255) / 256, 256>>>(W_hh, whhHiP, whhLoP, 1536 * 512);
    k_splitWoT<<<(512 * 256 + 255) / 256, 256>>>(Wo1);

    // init MLP
    k_concat<<<(int)(((size_t)NR * 160 + 255) / 256), 256>>>(z_q, f_pr);
    k_gemm_act<<<dim3(8, NR / 128), 256>>>(cP, 160, W1, 1024, b1, uP, 1024, 0);
    k_lngelu<<<NR, 256>>>(g1, be1);
    k_gemm_act<<<dim3(4, NR / 128), 256>>>(uP, 1024, W2, 512, b2, hAP, 512, 1);
    k_split<<<(NR * 512 + 255) / 256, 256>>>(hAP, hiAP, loAP, NR * 512);
    k_setx<<<NR / 256, 256>>>(start);

    // recurrence
    for (int t = 0; t < 20; ++t) {
        k_gru_mma<<<dim3(8, NR / 128), 256, GRU_SMEM>>>(W_ih, b_ih, b_hh, t);
        k_out_mma<<<dim3(4, NR / 128), 256, OUT_SMEM>>>(t);
        k_outfin<<<NR / 8, 256>>>(bo1, go, beo, Wo2, bo2, out, t);
    }
}